// round 1
// baseline (speedup 1.0000x reference)
#include <cuda_runtime.h>
#include <cuda_bf16.h>
#include <cstdint>

// Problem constants
#define BATCH 16
#define NN    1024
#define FF    128

// Scratch (device globals — no allocations allowed)
__device__ float g_dinv[BATCH * NN];            // 64 KB
__device__ float g_Ys[BATCH * NN * FF];         // 8 MB

// ---------------------------------------------------------------------------
// Kernel 1: dinv[b,n] = rsqrt( sum_m A[b,n,m] + 1 )
// One 256-thread block per row; each thread loads one float4 (row = 4 KB).
// ---------------------------------------------------------------------------
__global__ void __launch_bounds__(256) deg_kernel(const float* __restrict__ A) {
    const int row = blockIdx.x;  // 0 .. BATCH*NN-1
    const float4* Arow = reinterpret_cast<const float4*>(A + (size_t)row * NN);
    float4 v = Arow[threadIdx.x];
    float s = v.x + v.y + v.z + v.w;
    #pragma unroll
    for (int o = 16; o; o >>= 1) s += __shfl_xor_sync(0xFFFFFFFFu, s, o);
    __shared__ float ws[8];
    if ((threadIdx.x & 31) == 0) ws[threadIdx.x >> 5] = s;
    __syncthreads();
    if (threadIdx.x == 0) {
        float t = 0.f;
        #pragma unroll
        for (int i = 0; i < 8; i++) t += ws[i];
        g_dinv[row] = rsqrtf(t + 1.0f);
    }
}

// ---------------------------------------------------------------------------
// Shared SGEMM tiling parameters
//   BM=64, BN=128, BK=8, 256 threads, per-thread 8x4 accumulator
// ---------------------------------------------------------------------------
#define BM 64
#define BN 128
#define BK 8
#define TM 8
#define TN 4

// ---------------------------------------------------------------------------
// Kernel 2: Ys[r, :] = dinv[r] * (X[r, :] @ W)     r in [0, BATCH*NN)
//   M = 16384, K = 128, N = 128 (single flat GEMM, lda = 128)
// ---------------------------------------------------------------------------
__global__ void __launch_bounds__(256) gemm_xw(const float* __restrict__ X,
                                               const float* __restrict__ W) {
    __shared__ float As[BK][BM];
    __shared__ float Bs[BK][BN];

    const int tid  = threadIdx.x;
    const int tCol = tid & 31;   // 0..31
    const int tRow = tid >> 5;   // 0..7
    const int rowStart = blockIdx.y * BM;     // global row tile

    // Global-load mapping
    const int aRow = tid >> 2;          // 0..63
    const int aCol = (tid & 3) * 2;     // 0,2,4,6
    const int bRow = tid >> 5;          // 0..7
    const int bCol = (tid & 31) * 4;    // 0..124

    const float* Ap = X + (size_t)(rowStart + aRow) * FF + aCol;
    const float* Bp = W + (size_t)bRow * FF + bCol;

    float acc[TM][TN];
    #pragma unroll
    for (int i = 0; i < TM; i++)
        #pragma unroll
        for (int j = 0; j < TN; j++) acc[i][j] = 0.f;

    for (int k0 = 0; k0 < FF; k0 += BK) {
        float2 a2 = *reinterpret_cast<const float2*>(Ap); Ap += BK;
        As[aCol][aRow]     = a2.x;
        As[aCol + 1][aRow] = a2.y;
        float4 b4 = *reinterpret_cast<const float4*>(Bp); Bp += BK * FF;
        *reinterpret_cast<float4*>(&Bs[bRow][bCol]) = b4;
        __syncthreads();
        #pragma unroll
        for (int k = 0; k < BK; k++) {
            float4 m0 = *reinterpret_cast<float4*>(&As[k][tRow * TM]);
            float4 m1 = *reinterpret_cast<float4*>(&As[k][tRow * TM + 4]);
            float4 n0 = *reinterpret_cast<float4*>(&Bs[k][tCol * TN]);
            float rm[TM] = {m0.x, m0.y, m0.z, m0.w, m1.x, m1.y, m1.z, m1.w};
            float rn[TN] = {n0.x, n0.y, n0.z, n0.w};
            #pragma unroll
            for (int i = 0; i < TM; i++)
                #pragma unroll
                for (int j = 0; j < TN; j++) acc[i][j] = fmaf(rm[i], rn[j], acc[i][j]);
        }
        __syncthreads();
    }

    // Epilogue: scale by dinv[row], store to g_Ys
    const int row0 = rowStart + tRow * TM;
    const int col0 = tCol * TN;
    #pragma unroll
    for (int i = 0; i < TM; i++) {
        const int gr = row0 + i;
        const float di = g_dinv[gr];
        float4 o;
        o.x = di * acc[i][0];
        o.y = di * acc[i][1];
        o.z = di * acc[i][2];
        o.w = di * acc[i][3];
        *reinterpret_cast<float4*>(&g_Ys[(size_t)gr * FF + col0]) = o;
    }
}

// ---------------------------------------------------------------------------
// Kernel 3: out[b,n,:] = dinv[b,n] * ( A[b,n,:] @ Ys[b] + Ys[b,n,:] )
//   Per batch: M = 1024, K = 1024 (lda = 1024), N = 128
//   grid = (1, NN/BM, BATCH)
// ---------------------------------------------------------------------------
__global__ void __launch_bounds__(256) gemm_ays(const float* __restrict__ A,
                                                float* __restrict__ out) {
    __shared__ float As[BK][BM];
    __shared__ float Bs[BK][BN];

    const int tid  = threadIdx.x;
    const int tCol = tid & 31;
    const int tRow = tid >> 5;
    const int b        = blockIdx.z;
    const int rowStart = blockIdx.y * BM;   // row within batch

    const int aRow = tid >> 2;
    const int aCol = (tid & 3) * 2;
    const int bRow = tid >> 5;
    const int bCol = (tid & 31) * 4;

    const float* Ab  = A     + (size_t)b * NN * NN;
    const float* Ysb = g_Ys  + (size_t)b * NN * FF;

    const float* Ap = Ab  + (size_t)(rowStart + aRow) * NN + aCol;
    const float* Bp = Ysb + (size_t)bRow * FF + bCol;

    float acc[TM][TN];
    #pragma unroll
    for (int i = 0; i < TM; i++)
        #pragma unroll
        for (int j = 0; j < TN; j++) acc[i][j] = 0.f;

    for (int k0 = 0; k0 < NN; k0 += BK) {
        float2 a2 = *reinterpret_cast<const float2*>(Ap); Ap += BK;
        As[aCol][aRow]     = a2.x;
        As[aCol + 1][aRow] = a2.y;
        float4 b4 = *reinterpret_cast<const float4*>(Bp); Bp += BK * FF;
        *reinterpret_cast<float4*>(&Bs[bRow][bCol]) = b4;
        __syncthreads();
        #pragma unroll
        for (int k = 0; k < BK; k++) {
            float4 m0 = *reinterpret_cast<float4*>(&As[k][tRow * TM]);
            float4 m1 = *reinterpret_cast<float4*>(&As[k][tRow * TM + 4]);
            float4 n0 = *reinterpret_cast<float4*>(&Bs[k][tCol * TN]);
            float rm[TM] = {m0.x, m0.y, m0.z, m0.w, m1.x, m1.y, m1.z, m1.w};
            float rn[TN] = {n0.x, n0.y, n0.z, n0.w};
            #pragma unroll
            for (int i = 0; i < TM; i++)
                #pragma unroll
                for (int j = 0; j < TN; j++) acc[i][j] = fmaf(rm[i], rn[j], acc[i][j]);
        }
        __syncthreads();
    }

    // Epilogue: out = dinv * (acc + Ys_row)   (the +I term and row scaling)
    const int row0 = rowStart + tRow * TM;   // within batch
    const int col0 = tCol * TN;
    #pragma unroll
    for (int i = 0; i < TM; i++) {
        const int r  = row0 + i;
        const int gr = b * NN + r;
        const float di = g_dinv[gr];
        float4 ys = *reinterpret_cast<const float4*>(&Ysb[(size_t)r * FF + col0]);
        float4 o;
        o.x = di * (acc[i][0] + ys.x);
        o.y = di * (acc[i][1] + ys.y);
        o.z = di * (acc[i][2] + ys.z);
        o.w = di * (acc[i][3] + ys.w);
        *reinterpret_cast<float4*>(&out[(size_t)gr * FF + col0]) = o;
    }
}

// ---------------------------------------------------------------------------
// kernel_launch
// ---------------------------------------------------------------------------
extern "C" void kernel_launch(void* const* d_in, const int* in_sizes, int n_in,
                              void* d_out, int out_size) {
    const float* X = (const float*)d_in[0];   // [16,1024,128]
    const float* A = (const float*)d_in[1];   // [16,1024,1024]
    const float* W = (const float*)d_in[2];   // [128,128]
    float* out = (float*)d_out;               // [16,1024,128]

    // 1) degree + inverse-sqrt
    deg_kernel<<<BATCH * NN, 256>>>(A);

    // 2) Ys = dinv ⊙ (X @ W) : M=16384 flat
    {
        dim3 grid(1, (BATCH * NN) / BM, 1);
        gemm_xw<<<grid, 256>>>(X, W);
    }

    // 3) out = dinv ⊙ (A @ Ys + Ys), batched
    {
        dim3 grid(1, NN / BM, BATCH);
        gemm_ays<<<grid, 256>>>(A, out);
    }
}

// round 3
// speedup vs baseline: 1.9162x; 1.9162x over previous
#include <cuda_runtime.h>
#include <cuda_bf16.h>
#include <cstdint>

// Problem constants
#define BATCH 16
#define NN    1024
#define FF    128

// ---------------------------------------------------------------------------
// Device-global scratch (no allocations allowed)
// ---------------------------------------------------------------------------
__device__ float g_dinv[BATCH * NN];                         // 64 KB
__device__ __nv_bfloat16 g_YsT_hi[FF * BATCH * NN];          // 4 MB  [f][b*1024+m]
__device__ __nv_bfloat16 g_YsT_lo[FF * BATCH * NN];          // 4 MB

// ---------------------------------------------------------------------------
// Helpers
// ---------------------------------------------------------------------------
__device__ __forceinline__ uint32_t smem_to_u32(const void* p) {
    uint32_t a;
    asm("{ .reg .u64 t; cvta.to.shared.u64 t, %1; cvt.u32.u64 %0, t; }" : "=r"(a) : "l"(p));
    return a;
}

#define CP_ASYNC_16(dst_u32, src) \
    asm volatile("cp.async.cg.shared.global [%0], [%1], 16;" \
                 :: "r"(dst_u32), "l"(src) : "memory")
#define CP_ASYNC_COMMIT() asm volatile("cp.async.commit_group;" ::: "memory")
#define CP_ASYNC_WAIT_ALL() asm volatile("cp.async.wait_group 0;" ::: "memory")

__device__ __forceinline__ void mma_bf16(float* c, const uint32_t* a, const uint32_t* b) {
    asm volatile(
        "mma.sync.aligned.m16n8k16.row.col.f32.bf16.bf16.f32 "
        "{%0,%1,%2,%3}, {%4,%5,%6,%7}, {%8,%9}, {%0,%1,%2,%3};\n"
        : "+f"(c[0]), "+f"(c[1]), "+f"(c[2]), "+f"(c[3])
        : "r"(a[0]), "r"(a[1]), "r"(a[2]), "r"(a[3]), "r"(b[0]), "r"(b[1]));
}

// ---------------------------------------------------------------------------
// Kernel 1: dinv[row] = rsqrt( sum_m A[row, m] + 1 ).  Warp per row, MLP=8.
// ---------------------------------------------------------------------------
__global__ void __launch_bounds__(256) deg_kernel(const float* __restrict__ A) {
    const int row = blockIdx.x * 8 + (threadIdx.x >> 5);
    const int lid = threadIdx.x & 31;
    const float4* Ar = reinterpret_cast<const float4*>(A + (size_t)row * NN);
    float s = 0.f;
    #pragma unroll
    for (int i = 0; i < 8; i++) {
        float4 v = Ar[lid + i * 32];
        s += (v.x + v.y) + (v.z + v.w);
    }
    #pragma unroll
    for (int o = 16; o; o >>= 1) s += __shfl_xor_sync(0xFFFFFFFFu, s, o);
    if (lid == 0) g_dinv[row] = rsqrtf(s + 1.0f);
}

// ---------------------------------------------------------------------------
// Kernel 2: YsT[f, g] = d_g * sum_k W[k,f] * X[g,k],  g = b*1024+m (flat 16384)
// Written transposed + split into bf16 hi/lo (coalesced along g).
// Tile: 128 f x 128 g per block, K = 128, BK = 16.  grid.x = 128
// ---------------------------------------------------------------------------
__global__ void __launch_bounds__(256) gemm_xw_t(const float* __restrict__ X,
                                                 const float* __restrict__ W) {
    __shared__ float As[16][128];   // W slice:  As[kk][f]
    __shared__ float Bs[16][128];   // X^T slice: Bs[kk][m]

    const int tid = threadIdx.x;
    const int m0g = blockIdx.x * 128;
    const int f0 = (tid >> 4) * 8;
    const int m0 = (tid & 15) * 8;

    float acc[8][8];
    #pragma unroll
    for (int i = 0; i < 8; i++)
        #pragma unroll
        for (int j = 0; j < 8; j++) acc[i][j] = 0.f;

    for (int k0 = 0; k0 < FF; k0 += 16) {
        {   // W -> As (direct, coalesced)
            int idx = tid * 8;
            int kk = idx >> 7;
            int f = idx & 127;
            const float* wp = W + (size_t)(k0 + kk) * FF + f;
            float4 w0 = *reinterpret_cast<const float4*>(wp);
            float4 w1 = *reinterpret_cast<const float4*>(wp + 4);
            *reinterpret_cast<float4*>(&As[kk][f]) = w0;
            *reinterpret_cast<float4*>(&As[kk][f + 4]) = w1;
        }
        {   // X -> Bs transposed
            int m = tid >> 1;
            int half = tid & 1;
            const float* xp = X + (size_t)(m0g + m) * FF + k0 + half * 8;
            float4 x0 = *reinterpret_cast<const float4*>(xp);
            float4 x1 = *reinterpret_cast<const float4*>(xp + 4);
            int kb = half * 8;
            Bs[kb + 0][m] = x0.x; Bs[kb + 1][m] = x0.y;
            Bs[kb + 2][m] = x0.z; Bs[kb + 3][m] = x0.w;
            Bs[kb + 4][m] = x1.x; Bs[kb + 5][m] = x1.y;
            Bs[kb + 6][m] = x1.z; Bs[kb + 7][m] = x1.w;
        }
        __syncthreads();
        #pragma unroll
        for (int kk = 0; kk < 16; kk++) {
            float rf[8], rm[8];
            #pragma unroll
            for (int i = 0; i < 8; i++) rf[i] = As[kk][f0 + i];
            #pragma unroll
            for (int j = 0; j < 8; j++) rm[j] = Bs[kk][m0 + j];
            #pragma unroll
            for (int i = 0; i < 8; i++)
                #pragma unroll
                for (int j = 0; j < 8; j++) acc[i][j] = fmaf(rf[i], rm[j], acc[i][j]);
        }
        __syncthreads();
    }

    // Epilogue: column-scale by dinv, split to bf16 hi/lo, store transposed rows
    float dm[8];
    #pragma unroll
    for (int j = 0; j < 8; j++) dm[j] = g_dinv[m0g + m0 + j];
    #pragma unroll
    for (int i = 0; i < 8; i++) {
        uint32_t hp[4], lp[4];
        #pragma unroll
        for (int j = 0; j < 8; j += 2) {
            float v0 = acc[i][j] * dm[j];
            float v1 = acc[i][j + 1] * dm[j + 1];
            __nv_bfloat162 h = __floats2bfloat162_rn(v0, v1);
            float2 hf = __bfloat1622float2(h);
            __nv_bfloat162 l = __floats2bfloat162_rn(v0 - hf.x, v1 - hf.y);
            hp[j >> 1] = reinterpret_cast<uint32_t&>(h);
            lp[j >> 1] = reinterpret_cast<uint32_t&>(l);
        }
        size_t dst = (size_t)(f0 + i) * (BATCH * NN) + m0g + m0;
        *reinterpret_cast<uint4*>(&g_YsT_hi[dst]) = make_uint4(hp[0], hp[1], hp[2], hp[3]);
        *reinterpret_cast<uint4*>(&g_YsT_lo[dst]) = make_uint4(lp[0], lp[1], lp[2], lp[3]);
    }
}

// ---------------------------------------------------------------------------
// Kernel 3: out[b,n,:] = d_n * ( (A+I)[b,n,:] @ Ys[b] )   via mma.sync bf16
//   error-compensated split: Ah*Bh + Ah*Bl + Al*Bh, fp32 accum.
//   CTA tile 128x128, K-chunk 32, double-buffered smem.
//   8 warps = 2(m) x 4(n);  warp tile 64x32 -> 4x4 m16n8k16 tiles.
// ---------------------------------------------------------------------------
// smem layout per buffer (rows padded to 80B): Ah @0, Al @10240, Bh @20480, Bl @30720
#define ROWB 80
#define TILE_SZ (128 * ROWB)       // 10240
#define BUF_SZ (4 * TILE_SZ)       // 40960
#define SMEM3 (2 * BUF_SZ)         // 81920

__global__ void __launch_bounds__(256, 1) gemm_mma(const float* __restrict__ A,
                                                   float* __restrict__ out) {
    extern __shared__ char smem_raw[];
    char* sm = smem_raw;
    const uint32_t sbase = smem_to_u32(sm);

    const int tid = threadIdx.x;
    const int wid = tid >> 5, lane = tid & 31;
    const int g = lane >> 2, tig = lane & 3;
    const int wm = wid & 1, wn = wid >> 1;
    const int b = blockIdx.y;
    const int rowStart = blockIdx.x * 128;

    // ---- A staging mapping: thread covers rows (tid>>3)+i*32, float4 at col (tid&7)*4
    const int arow = tid >> 3;
    const int akg = tid & 7;
    const float* aptr = A + ((size_t)b * NN + rowStart + arow) * NN + akg * 4;

    // ---- B cp.async mapping: f = (tid>>2)+i*64, 16B at k-offset (tid&3)*8
    const int bf = tid >> 2;
    const int bkg = tid & 3;
    const size_t GTOT = (size_t)BATCH * NN;
    const __nv_bfloat16* bhp = g_YsT_hi + (size_t)bf * GTOT + (size_t)b * NN + bkg * 8;
    const __nv_bfloat16* blp = g_YsT_lo + (size_t)bf * GTOT + (size_t)b * NN + bkg * 8;

    float acc[4][4][4];
    #pragma unroll
    for (int i = 0; i < 4; i++)
        #pragma unroll
        for (int j = 0; j < 4; j++)
            #pragma unroll
            for (int k = 0; k < 4; k++) acc[i][j][k] = 0.f;

    float4 av[4];

    auto cp_B = [&](int kc, int buf) {
        const uint32_t bb = sbase + buf * BUF_SZ;
        #pragma unroll
        for (int i = 0; i < 2; i++) {
            const uint32_t off = (bf + i * 64) * ROWB + bkg * 16;
            CP_ASYNC_16(bb + 2 * TILE_SZ + off, bhp + (size_t)i * 64 * GTOT + kc * 32);
            CP_ASYNC_16(bb + 3 * TILE_SZ + off, blp + (size_t)i * 64 * GTOT + kc * 32);
        }
    };
    auto ldg_A = [&](int kc) {
        #pragma unroll
        for (int i = 0; i < 4; i++)
            av[i] = *reinterpret_cast<const float4*>(aptr + (size_t)i * 32 * NN + kc * 32);
    };
    auto sts_A = [&](int kc, int buf) {
        char* base = sm + buf * BUF_SZ;
        #pragma unroll
        for (int i = 0; i < 4; i++) {
            float4 x = av[i];
            const int row = arow + i * 32;
            const int d = (rowStart + row) - (kc * 32 + akg * 4);
            if ((unsigned)d < 4u) (&x.x)[d] += 1.0f;   // +I on the diagonal
            __nv_bfloat162 h01 = __floats2bfloat162_rn(x.x, x.y);
            __nv_bfloat162 h23 = __floats2bfloat162_rn(x.z, x.w);
            float2 f01 = __bfloat1622float2(h01);
            float2 f23 = __bfloat1622float2(h23);
            __nv_bfloat162 l01 = __floats2bfloat162_rn(x.x - f01.x, x.y - f01.y);
            __nv_bfloat162 l23 = __floats2bfloat162_rn(x.z - f23.x, x.w - f23.y);
            const uint32_t off = row * ROWB + akg * 8;
            *reinterpret_cast<uint2*>(base + off) =
                make_uint2(reinterpret_cast<uint32_t&>(h01), reinterpret_cast<uint32_t&>(h23));
            *reinterpret_cast<uint2*>(base + TILE_SZ + off) =
                make_uint2(reinterpret_cast<uint32_t&>(l01), reinterpret_cast<uint32_t&>(l23));
        }
    };

    // ---- prologue: stage chunk 0 into buffer 0
    cp_B(0, 0);
    CP_ASYNC_COMMIT();
    ldg_A(0);
    sts_A(0, 0);
    CP_ASYNC_WAIT_ALL();
    __syncthreads();

    for (int kc = 0; kc < NN / 32; kc++) {
        const int buf = kc & 1;
        const bool more = (kc + 1 < NN / 32);
        if (more) {
            cp_B(kc + 1, buf ^ 1);     // buf^1 fully consumed before last sync
            CP_ASYNC_COMMIT();
            ldg_A(kc + 1);
        }

        char* Ah = sm + buf * BUF_SZ;
        char* Al = Ah + TILE_SZ;
        char* Bh = Ah + 2 * TILE_SZ;
        char* Bl = Ah + 3 * TILE_SZ;

        #pragma unroll
        for (int ks = 0; ks < 2; ks++) {
            const int kb = ks * 32 + tig * 4;   // byte offset of this thread's k-pair
            uint32_t ah[4][4], al[4][4], bh2[4][2], bl2[4][2];
            #pragma unroll
            for (int mt = 0; mt < 4; mt++) {
                const uint32_t o = (wm * 64 + mt * 16 + g) * ROWB + kb;
                ah[mt][0] = *reinterpret_cast<uint32_t*>(Ah + o);
                ah[mt][1] = *reinterpret_cast<uint32_t*>(Ah + o + 8 * ROWB);
                ah[mt][2] = *reinterpret_cast<uint32_t*>(Ah + o + 16);
                ah[mt][3] = *reinterpret_cast<uint32_t*>(Ah + o + 8 * ROWB + 16);
                al[mt][0] = *reinterpret_cast<uint32_t*>(Al + o);
                al[mt][1] = *reinterpret_cast<uint32_t*>(Al + o + 8 * ROWB);
                al[mt][2] = *reinterpret_cast<uint32_t*>(Al + o + 16);
                al[mt][3] = *reinterpret_cast<uint32_t*>(Al + o + 8 * ROWB + 16);
            }
            #pragma unroll
            for (int nt = 0; nt < 4; nt++) {
                const uint32_t o = (wn * 32 + nt * 8 + g) * ROWB + kb;
                bh2[nt][0] = *reinterpret_cast<uint32_t*>(Bh + o);
                bh2[nt][1] = *reinterpret_cast<uint32_t*>(Bh + o + 16);
                bl2[nt][0] = *reinterpret_cast<uint32_t*>(Bl + o);
                bl2[nt][1] = *reinterpret_cast<uint32_t*>(Bl + o + 16);
            }
            #pragma unroll
            for (int mt = 0; mt < 4; mt++)
                #pragma unroll
                for (int nt = 0; nt < 4; nt++) {
                    mma_bf16(acc[mt][nt], ah[mt], bh2[nt]);
                    mma_bf16(acc[mt][nt], ah[mt], bl2[nt]);
                    mma_bf16(acc[mt][nt], al[mt], bh2[nt]);
                }
        }

        if (more) sts_A(kc + 1, buf ^ 1);
        CP_ASYNC_WAIT_ALL();
        __syncthreads();
    }

    // ---- epilogue: scale by dinv row factor, write fp32
    #pragma unroll
    for (int mt = 0; mt < 4; mt++) {
        const int r0 = b * NN + rowStart + wm * 64 + mt * 16 + g;
        const float d0 = g_dinv[r0];
        const float d1 = g_dinv[r0 + 8];
        float* p0 = out + (size_t)r0 * FF + wn * 32 + tig * 2;
        float* p1 = p0 + (size_t)8 * FF;
        #pragma unroll
        for (int nt = 0; nt < 4; nt++) {
            float2 v0, v1;
            v0.x = acc[mt][nt][0] * d0;
            v0.y = acc[mt][nt][1] * d0;
            v1.x = acc[mt][nt][2] * d1;
            v1.y = acc[mt][nt][3] * d1;
            *reinterpret_cast<float2*>(p0 + nt * 8) = v0;
            *reinterpret_cast<float2*>(p1 + nt * 8) = v1;
        }
    }
}

// ---------------------------------------------------------------------------
// kernel_launch
// ---------------------------------------------------------------------------
extern "C" void kernel_launch(void* const* d_in, const int* in_sizes, int n_in,
                              void* d_out, int out_size) {
    const float* X = (const float*)d_in[0];   // [16,1024,128]
    const float* A = (const float*)d_in[1];   // [16,1024,1024]
    const float* W = (const float*)d_in[2];   // [128,128]
    float* out = (float*)d_out;               // [16,1024,128]

    cudaFuncSetAttribute(gemm_mma, cudaFuncAttributeMaxDynamicSharedMemorySize, SMEM3);

    // 1) dinv = rsqrt(rowsum(A) + 1)
    deg_kernel<<<(BATCH * NN) / 8, 256>>>(A);

    // 2) YsT (bf16 hi/lo, transposed, dinv-scaled) = (X @ W)^T * d
    gemm_xw_t<<<(BATCH * NN) / 128, 256>>>(X, W);

    // 3) out = dinv ⊙ ((A+I) @ Ys)   via mma.sync bf16 split
    {
        dim3 grid(NN / 128, BATCH);
        gemm_mma<<<grid, 256, SMEM3>>>(A, out);
    }
}